// round 8
// baseline (speedup 1.0000x reference)
#include <cuda_runtime.h>
#include <cuda_bf16.h>

// BoundaryLoss: mean(sigmoid(logits) * EDT2D(target)), [8,1,256,256].
//
// Single fused kernel. Each CTA owns 4 output rows of one image:
//   Phase A: warp shuffle-scan exact 1D row distance^2 for the 12-row halo
//            window (4 own + +-4) into smem. Out-of-image rows = BIG.
//   Phase B: per-thread float4 column window min over smem (r = 0..4).
//            Rare exact tail (cur > 25): dr2 computed on-the-fly from
//            `target` with a bounded outward scan -- exact, no scratch.
//   Reduce:  per-block partial -> last-arriving block (monotonic counter,
//            graph-replay safe) reduces 512 partials deterministically.

#define B 8
#define H 256
#define W 256
#define NPIX (B * H * W)
#define BIGD 1000000.0f
#define FULL 0xffffffffu
#define TROWS 4
#define HALO 4
#define LROWS (TROWS + 2 * HALO)      // 12
#define NBLK (B * H / TROWS)          // 512

__device__ float    g_part[NBLK];
__device__ unsigned g_done = 0u;      // monotonic across graph replays

// Exact dr2 for one pixel, scanned outward from w; returns >= bound if the
// true dr2 >= bound (then it cannot improve the running min).
__device__ __forceinline__ float dr2_otf(const int* __restrict__ trow,
                                         int w, float bound)
{
    for (int t = 0; (float)(t * t) < bound; ++t) {
        bool hit = false;
        if (w - t >= 0 && trow[w - t] > 0) hit = true;
        if (w + t < W && trow[w + t] > 0) hit = true;
        if (hit) return (float)(t * t);
    }
    return BIGD;
}

__global__ __launch_bounds__(256, 4)
void k_fused(const float* __restrict__ logits,
             const int* __restrict__ target,
             float* __restrict__ out)
{
    __shared__ float sdr[LROWS][W];   // 12 KB halo strip of dr2
    __shared__ float ws[8];
    __shared__ int   s_last;

    const int tid  = threadIdx.x;
    const int lane = tid & 31;
    const int warp = tid >> 5;
    const int b    = blockIdx.x >> 6;            // 64 tiles per image
    const int r0   = (blockIdx.x & 63) * TROWS;  // first output row

    // ================= Phase A: dr2 halo strip =================
    // warps 0..3 -> local rows {2w, 2w+1}; warps 4..7 -> local row {4+w}
    const int nl = (warp < 4) ? 2 : 1;
    for (int q = 0; q < nl; ++q) {
        const int l  = (warp < 4) ? (2 * warp + q) : (4 + warp);
        const int g  = r0 - HALO + l;            // global image row
        const int w0 = lane << 3;                // 8 px per lane

        if (g < 0 || g >= H) {
            const float4 bv = make_float4(BIGD, BIGD, BIGD, BIGD);
            *reinterpret_cast<float4*>(&sdr[l][w0])     = bv;
            *reinterpret_cast<float4*>(&sdr[l][w0 + 4]) = bv;
            continue;
        }

        const int4* tp = reinterpret_cast<const int4*>(target + (b * H + g) * W + w0);
        const int4 t0 = tp[0];
        const int4 t1 = tp[1];
        int fg[8];
        fg[0] = t0.x > 0; fg[1] = t0.y > 0; fg[2] = t0.z > 0; fg[3] = t0.w > 0;
        fg[4] = t1.x > 0; fg[5] = t1.y > 0; fg[6] = t1.z > 0; fg[7] = t1.w > 0;

        // nearest fg <= w : prefix max of (fg? w : -1)
        int pl[8];
        int run = -1;
#pragma unroll
        for (int k = 0; k < 8; ++k) {
            const int cand = fg[k] ? (w0 + k) : -1;
            run = max(run, cand);
            pl[k] = run;
        }
        int x = run;
#pragma unroll
        for (int off = 1; off < 32; off <<= 1) {
            const int y = __shfl_up_sync(FULL, x, off);
            if (lane >= off) x = max(x, y);
        }
        int exl = __shfl_up_sync(FULL, x, 1);
        if (lane == 0) exl = -1;

        // nearest fg >= w : suffix min of (fg? w : 512)
        int pr[8];
        int run2 = 512;
#pragma unroll
        for (int k = 7; k >= 0; --k) {
            const int cand = fg[k] ? (w0 + k) : 512;
            run2 = min(run2, cand);
            pr[k] = run2;
        }
        int x2 = run2;
#pragma unroll
        for (int off = 1; off < 32; off <<= 1) {
            const int y = __shfl_down_sync(FULL, x2, off);
            if (lane + off < 32) x2 = min(x2, y);
        }
        int exr = __shfl_down_sync(FULL, x2, 1);
        if (lane == 31) exr = 512;

        float o[8];
#pragma unroll
        for (int k = 0; k < 8; ++k) {
            const int L = max(pl[k], exl);
            const int R = min(pr[k], exr);
            const float dl = (L >= 0)  ? (float)(w0 + k - L) : BIGD;
            const float dr = (R < 512) ? (float)(R - (w0 + k)) : BIGD;
            const float d  = fminf(dl, dr);
            o[k] = d * d;
        }
        *reinterpret_cast<float4*>(&sdr[l][w0])     = make_float4(o[0], o[1], o[2], o[3]);
        *reinterpret_cast<float4*>(&sdr[l][w0 + 4]) = make_float4(o[4], o[5], o[6], o[7]);
    }
    __syncthreads();

    // ================= Phase B: window min + loss =================
    const int lr = tid >> 6;            // 0..3 : output row within tile
    const int c4 = tid & 63;            // float4 column
    const int i  = r0 + lr;             // global image row
    const int sr = lr + HALO;           // smem row of own dr2

    float4 cur = *reinterpret_cast<const float4*>(&sdr[sr][c4 * 4]);
#pragma unroll
    for (int r = 1; r <= 4; ++r) {
        const float rr = (float)(r * r);
        const float4 u = *reinterpret_cast<const float4*>(&sdr[sr - r][c4 * 4]);
        const float4 d = *reinterpret_cast<const float4*>(&sdr[sr + r][c4 * 4]);
        cur.x = fminf(cur.x, fminf(u.x, d.x) + rr);
        cur.y = fminf(cur.y, fminf(u.y, d.y) + rr);
        cur.z = fminf(cur.z, fminf(u.z, d.z) + rr);
        cur.w = fminf(cur.w, fminf(u.w, d.w) + rr);
    }

    // rare exact tail: r >= 5, dr2 on the fly from target
    if (fmaxf(fmaxf(cur.x, cur.y), fmaxf(cur.z, cur.w)) > 25.0f) {
        float* c = &cur.x;
#pragma unroll
        for (int q = 0; q < 4; ++q) {
            const int w = c4 * 4 + q;
            for (int r = 5; r < H && (float)(r * r) < c[q]; ++r) {
                const float rr = (float)(r * r);
                if (i - r >= 0)
                    c[q] = fminf(c[q], dr2_otf(target + (b * H + i - r) * W, w, c[q] - rr) + rr);
                if (i + r < H)
                    c[q] = fminf(c[q], dr2_otf(target + (b * H + i + r) * W, w, c[q] - rr) + rr);
            }
        }
    }

    const float4 xv =
        reinterpret_cast<const float4*>(logits)[(b * H + i) * (W / 4) + c4];
    const float px = 1.0f / (1.0f + __expf(-xv.x));
    const float py = 1.0f / (1.0f + __expf(-xv.y));
    const float pz = 1.0f / (1.0f + __expf(-xv.z));
    const float pw = 1.0f / (1.0f + __expf(-xv.w));

    float acc = px * sqrtf(cur.x) + py * sqrtf(cur.y)
              + pz * sqrtf(cur.z) + pw * sqrtf(cur.w);
    acc *= (1.0f / (float)NPIX);

    // ================= block partial =================
#pragma unroll
    for (int o = 16; o; o >>= 1)
        acc += __shfl_xor_sync(FULL, acc, o);
    if (lane == 0) ws[warp] = acc;
    __syncthreads();

    if (tid == 0) {
        float t = ws[0];
#pragma unroll
        for (int k = 1; k < 8; ++k) t += ws[k];
        g_part[blockIdx.x] = t;
        __threadfence();                         // release partial
        const unsigned prev = atomicAdd(&g_done, 1u);
        s_last = ((prev % NBLK) == NBLK - 1u);   // last block of this replay
    }
    __syncthreads();

    // ================= final reduce by last block =================
    if (s_last) {
        __threadfence();                         // acquire partials
        const volatile float* vp = g_part;
        float v = vp[tid] + vp[tid + 256];
#pragma unroll
        for (int o = 16; o; o >>= 1)
            v += __shfl_xor_sync(FULL, v, o);
        __syncthreads();                         // ws reuse
        if (lane == 0) ws[warp] = v;
        __syncthreads();
        if (tid == 0) {
            float t = ws[0];
#pragma unroll
            for (int k = 1; k < 8; ++k) t += ws[k];
            *out = t;
        }
    }
}

extern "C" void kernel_launch(void* const* d_in, const int* in_sizes, int n_in,
                              void* d_out, int out_size)
{
    const float* logits = (const float*)d_in[0];
    const int*   target = (const int*)d_in[1];
    float*       out    = (float*)d_out;

    k_fused<<<NBLK, 256>>>(logits, target, out);
}

// round 9
// speedup vs baseline: 1.2043x; 1.2043x over previous
#include <cuda_runtime.h>
#include <cuda_bf16.h>

// BoundaryLoss: mean(sigmoid(logits) * EDT2D(target)), [8,1,256,256].
//
// Stage 1 (k_rowdist): warp-per-row exact 1D row distance^2 via shuffle
//   scans into PADDED scratch [B][H+8][W] (4 BIG guard rows top+bottom per
//   image, written by blocks 0..7). Guards make stage 2 branch-free.
// Stage 2 (k_edt_loss): 1 thread = 4 px (float4). Exact column min
//   D2(i,w) = min_j dr2[j,w] + (i-j)^2 as 9 UNCONDITIONAL vector loads at
//   constant offsets (j in [i-4, i+4]) + cold exact tail for cur > 25.
//   Fused sigmoid + block reduction + one atomicAdd per CTA.

#define B 8
#define H 256
#define HP (H + 8)                // padded rows per image
#define W 256
#define NPIX (B * H * W)          // 524288
#define NV4  (NPIX / 4)           // 131072 float4 tasks
#define BIGD 1000000.0f
#define FULL 0xffffffffu
#define RW4 (W / 4)               // 64 float4 per row

__device__ float g_dr2p[B * HP * W];   // padded squared 1D row distances

__global__ void k_rowdist(const int* __restrict__ target,
                          float* __restrict__ out)
{
    if (blockIdx.x == 0 && threadIdx.x == 0) *out = 0.0f;

    const int tid  = threadIdx.x;
    const int lane = tid & 31;
    const int warp = tid >> 5;

    // blocks 0..7: also write BIG guard rows for image blockIdx.x
    if (blockIdx.x < B) {
        const int b = blockIdx.x;
        const float4 bv = make_float4(BIGD, BIGD, BIGD, BIGD);
        float4* gp = reinterpret_cast<float4*>(g_dr2p);
#pragma unroll
        for (int g = tid; g < 512; g += 256) {     // 8 guard rows x 64 f4
            const int rg = g >> 6;                 // 0..7
            const int c  = g & 63;
            const int pr = (rg < 4) ? rg : (H + rg);   // padded row
            gp[(b * HP + pr) * RW4 + c] = bv;
        }
    }

    const int row = blockIdx.x * 8 + warp;         // 0..2047
    const int b   = row >> 8;
    const int i   = row & (H - 1);
    const int w0  = lane << 3;                     // 8 px per lane

    const int4* tp = reinterpret_cast<const int4*>(target + row * W + w0);
    const int4 t0 = tp[0];
    const int4 t1 = tp[1];
    int fg[8];
    fg[0] = t0.x > 0; fg[1] = t0.y > 0; fg[2] = t0.z > 0; fg[3] = t0.w > 0;
    fg[4] = t1.x > 0; fg[5] = t1.y > 0; fg[6] = t1.z > 0; fg[7] = t1.w > 0;

    // nearest fg <= w : prefix max of (fg? w : -1)
    int pl[8];
    int run = -1;
#pragma unroll
    for (int k = 0; k < 8; ++k) {
        const int cand = fg[k] ? (w0 + k) : -1;
        run = max(run, cand);
        pl[k] = run;
    }
    int x = run;
#pragma unroll
    for (int off = 1; off < 32; off <<= 1) {
        const int y = __shfl_up_sync(FULL, x, off);
        if (lane >= off) x = max(x, y);
    }
    int exl = __shfl_up_sync(FULL, x, 1);
    if (lane == 0) exl = -1;

    // nearest fg >= w : suffix min of (fg? w : 512)
    int pr[8];
    int run2 = 512;
#pragma unroll
    for (int k = 7; k >= 0; --k) {
        const int cand = fg[k] ? (w0 + k) : 512;
        run2 = min(run2, cand);
        pr[k] = run2;
    }
    int x2 = run2;
#pragma unroll
    for (int off = 1; off < 32; off <<= 1) {
        const int y = __shfl_down_sync(FULL, x2, off);
        if (lane + off < 32) x2 = min(x2, y);
    }
    int exr = __shfl_down_sync(FULL, x2, 1);
    if (lane == 31) exr = 512;

    float o[8];
#pragma unroll
    for (int k = 0; k < 8; ++k) {
        const int L = max(pl[k], exl);
        const int R = min(pr[k], exr);
        const float dl = (L >= 0)  ? (float)(w0 + k - L) : BIGD;
        const float dr = (R < 512) ? (float)(R - (w0 + k)) : BIGD;
        const float d  = fminf(dl, dr);
        o[k] = d * d;
    }
    float4* op = reinterpret_cast<float4*>(g_dr2p + (b * HP + i + 4) * W + w0);
    op[0] = make_float4(o[0], o[1], o[2], o[3]);
    op[1] = make_float4(o[4], o[5], o[6], o[7]);
}

__device__ __forceinline__ float4 fmin4a(float4 a, float4 bu, float4 bd, float rr)
{
    a.x = fminf(a.x, fminf(bu.x, bd.x) + rr);
    a.y = fminf(a.y, fminf(bu.y, bd.y) + rr);
    a.z = fminf(a.z, fminf(bu.z, bd.z) + rr);
    a.w = fminf(a.w, fminf(bu.w, bd.w) + rr);
    return a;
}

__global__ void k_edt_loss(const float* __restrict__ logits,
                           float* __restrict__ out)
{
    const int v   = blockIdx.x * blockDim.x + threadIdx.x;  // float4 task
    const int b   = v >> 14;
    const int rem = v & 16383;
    const int i   = rem >> 6;                               // image row
    const int c4  = rem & 63;

    const float4* dr = reinterpret_cast<const float4*>(g_dr2p);
    const int pv = (b * HP + i + 4) * RW4 + c4;             // padded f4 idx

    const float4 xv = reinterpret_cast<const float4*>(logits)[v];

    // 9 unconditional vector loads (guards absorb boundaries)
    float4 cur = dr[pv];
    const float4 u1 = dr[pv - 1 * RW4];
    const float4 d1 = dr[pv + 1 * RW4];
    const float4 u2 = dr[pv - 2 * RW4];
    const float4 d2 = dr[pv + 2 * RW4];
    const float4 u3 = dr[pv - 3 * RW4];
    const float4 d3 = dr[pv + 3 * RW4];
    const float4 u4 = dr[pv - 4 * RW4];
    const float4 d4 = dr[pv + 4 * RW4];

    cur = fmin4a(cur, u1, d1, 1.0f);
    cur = fmin4a(cur, u2, d2, 4.0f);
    cur = fmin4a(cur, u3, d3, 9.0f);
    cur = fmin4a(cur, u4, d4, 16.0f);

    // cold exact tail: r >= 5 (never taken at 50% fg density, kept exact)
    if (__builtin_expect(
            fmaxf(fmaxf(cur.x, cur.y), fmaxf(cur.z, cur.w)) > 25.0f, 0)) {
        float* c = &cur.x;
#pragma unroll
        for (int q = 0; q < 4; ++q) {
            const int w = c4 * 4 + q;
            for (int r = 5; r < H && (float)(r * r) < c[q]; ++r) {
                const float rr = (float)(r * r);
                if (i >= r)
                    c[q] = fminf(c[q],
                        g_dr2p[(b * HP + (i - r) + 4) * W + w] + rr);
                if (i + r < H)
                    c[q] = fminf(c[q],
                        g_dr2p[(b * HP + (i + r) + 4) * W + w] + rr);
            }
        }
    }

    const float px = 1.0f / (1.0f + __expf(-xv.x));
    const float py = 1.0f / (1.0f + __expf(-xv.y));
    const float pz = 1.0f / (1.0f + __expf(-xv.z));
    const float pw = 1.0f / (1.0f + __expf(-xv.w));

    float val = px * sqrtf(cur.x) + py * sqrtf(cur.y)
              + pz * sqrtf(cur.z) + pw * sqrtf(cur.w);
    val *= (1.0f / (float)NPIX);

    // block reduction -> one atomic per CTA
#pragma unroll
    for (int o = 16; o; o >>= 1)
        val += __shfl_xor_sync(FULL, val, o);

    __shared__ float ws[8];
    if ((threadIdx.x & 31) == 0) ws[threadIdx.x >> 5] = val;
    __syncthreads();
    if (threadIdx.x == 0) {
        float t = ws[0];
#pragma unroll
        for (int k = 1; k < 8; ++k) t += ws[k];
        atomicAdd(out, t);
    }
}

extern "C" void kernel_launch(void* const* d_in, const int* in_sizes, int n_in,
                              void* d_out, int out_size)
{
    const float* logits = (const float*)d_in[0];
    const int*   target = (const int*)d_in[1];
    float*       out    = (float*)d_out;

    k_rowdist<<<(B * H) / 8, 256>>>(target, out);
    k_edt_loss<<<NV4 / 256, 256>>>(logits, out);
}

// round 10
// speedup vs baseline: 1.2399x; 1.0295x over previous
#include <cuda_runtime.h>
#include <cuda_bf16.h>

// BoundaryLoss: mean(sigmoid(logits) * EDT2D(target)), [8,1,256,256].
//
// Stage 1 (k_rowdist): warp-per-row exact 1D row distance^2 (shuffle scans)
//   -> g_dr2; fires PDL trigger right after its stores.
// Stage 2 (k_edt_loss): launched with PDL (programmatic stream
//   serialization). Prelude (index math + logits load + sigmoid) runs
//   overlapped with stage 1; cudaGridDependencySynchronize() before the
//   dr2-dependent window loads. Exact column min via 9-row batched window
//   (MLP) + rare exact expand tail; block reduce + one atomicAdd per CTA.

#define B 8
#define H 256
#define W 256
#define NPIX (B * H * W)          // 524288
#define NV4  (NPIX / 4)           // 131072 float4 tasks
#define BIGD 1000000.0f
#define FULL 0xffffffffu
#define RW4 (W / 4)               // 64 float4 per row

__device__ float g_dr2[NPIX];     // squared 1D row distances

__global__ void k_rowdist(const int* __restrict__ target,
                          float* __restrict__ out)
{
    if (blockIdx.x == 0 && threadIdx.x == 0) *out = 0.0f;

    const int lane = threadIdx.x & 31;
    const int warp = threadIdx.x >> 5;
    const int row  = (blockIdx.x << 3) + warp;     // 8 rows per block
    const int base = row * W;
    const int w0   = lane << 3;                    // 8 px per lane

    const int4* tp = reinterpret_cast<const int4*>(target + base + w0);
    const int4 t0 = tp[0];
    const int4 t1 = tp[1];
    int fg[8];
    fg[0] = t0.x > 0; fg[1] = t0.y > 0; fg[2] = t0.z > 0; fg[3] = t0.w > 0;
    fg[4] = t1.x > 0; fg[5] = t1.y > 0; fg[6] = t1.z > 0; fg[7] = t1.w > 0;

    // nearest fg <= w : prefix max of (fg? w : -1)
    int pl[8];
    int run = -1;
#pragma unroll
    for (int k = 0; k < 8; ++k) {
        const int cand = fg[k] ? (w0 + k) : -1;
        run = max(run, cand);
        pl[k] = run;
    }
    int x = run;
#pragma unroll
    for (int off = 1; off < 32; off <<= 1) {
        const int y = __shfl_up_sync(FULL, x, off);
        if (lane >= off) x = max(x, y);
    }
    int exl = __shfl_up_sync(FULL, x, 1);
    if (lane == 0) exl = -1;

    // nearest fg >= w : suffix min of (fg? w : 512)
    int pr[8];
    int run2 = 512;
#pragma unroll
    for (int k = 7; k >= 0; --k) {
        const int cand = fg[k] ? (w0 + k) : 512;
        run2 = min(run2, cand);
        pr[k] = run2;
    }
    int x2 = run2;
#pragma unroll
    for (int off = 1; off < 32; off <<= 1) {
        const int y = __shfl_down_sync(FULL, x2, off);
        if (lane + off < 32) x2 = min(x2, y);
    }
    int exr = __shfl_down_sync(FULL, x2, 1);
    if (lane == 31) exr = 512;

    float o[8];
#pragma unroll
    for (int k = 0; k < 8; ++k) {
        const int L = max(pl[k], exl);
        const int R = min(pr[k], exr);
        const float dl = (L >= 0)  ? (float)(w0 + k - L) : BIGD;
        const float dr = (R < 512) ? (float)(R - (w0 + k)) : BIGD;
        const float d  = fminf(dl, dr);
        o[k] = d * d;
    }
    float4* op = reinterpret_cast<float4*>(g_dr2 + base + w0);
    op[0] = make_float4(o[0], o[1], o[2], o[3]);
    op[1] = make_float4(o[4], o[5], o[6], o[7]);

    // allow dependent kernel's prelude to start while this grid drains
    cudaTriggerProgrammaticLaunchCompletion();
}

__device__ __forceinline__ float4 fmin4a(float4 a, float4 bu, float4 bd, float rr)
{
    a.x = fminf(a.x, fminf(bu.x, bd.x) + rr);
    a.y = fminf(a.y, fminf(bu.y, bd.y) + rr);
    a.z = fminf(a.z, fminf(bu.z, bd.z) + rr);
    a.w = fminf(a.w, fminf(bu.w, bd.w) + rr);
    return a;
}

__global__ void k_edt_loss(const float* __restrict__ logits,
                           float* __restrict__ out)
{
    const int v = blockIdx.x * blockDim.x + threadIdx.x;   // float4 task
    const int i = (v / RW4) & (H - 1);                     // row within image

    // ---- prelude: independent of stage 1 (overlaps with it via PDL) ----
    const float4 xv = reinterpret_cast<const float4*>(logits)[v];
    const float px = 1.0f / (1.0f + __expf(-xv.x));
    const float py = 1.0f / (1.0f + __expf(-xv.y));
    const float pz = 1.0f / (1.0f + __expf(-xv.z));
    const float pw = 1.0f / (1.0f + __expf(-xv.w));

    // ---- wait for stage 1's g_dr2 to be globally visible ----
    cudaGridDependencySynchronize();

    const float4* dr  = reinterpret_cast<const float4*>(g_dr2);
    const float4  big = make_float4(BIGD, BIGD, BIGD, BIGD);

    // batch phase: 9 independent vector loads covering j in [i-4, i+4]
    float4 cur = dr[v];
    const float4 u1 = (i >= 1)    ? dr[v - 1 * RW4] : big;
    const float4 d1 = (i + 1 < H) ? dr[v + 1 * RW4] : big;
    const float4 u2 = (i >= 2)    ? dr[v - 2 * RW4] : big;
    const float4 d2 = (i + 2 < H) ? dr[v + 2 * RW4] : big;
    const float4 u3 = (i >= 3)    ? dr[v - 3 * RW4] : big;
    const float4 d3 = (i + 3 < H) ? dr[v + 3 * RW4] : big;
    const float4 u4 = (i >= 4)    ? dr[v - 4 * RW4] : big;
    const float4 d4 = (i + 4 < H) ? dr[v + 4 * RW4] : big;

    cur = fmin4a(cur, u1, d1, 1.0f);
    cur = fmin4a(cur, u2, d2, 4.0f);
    cur = fmin4a(cur, u3, d3, 9.0f);
    cur = fmin4a(cur, u4, d4, 16.0f);

    // rare exact tail: r >= 5, scalar per component
    if (fmaxf(fmaxf(cur.x, cur.y), fmaxf(cur.z, cur.w)) > 25.0f) {
        float* c = &cur.x;
        const int p0 = v << 2;
#pragma unroll
        for (int q = 0; q < 4; ++q) {
            for (int r = 5; r < H && (float)(r * r) < c[q]; ++r) {
                const float rr = (float)(r * r);
                if (i >= r)    c[q] = fminf(c[q], g_dr2[p0 + q - (r << 8)] + rr);
                if (i + r < H) c[q] = fminf(c[q], g_dr2[p0 + q + (r << 8)] + rr);
            }
        }
    }

    float val = px * sqrtf(cur.x) + py * sqrtf(cur.y)
              + pz * sqrtf(cur.z) + pw * sqrtf(cur.w);
    val *= (1.0f / (float)NPIX);

    // block reduction -> one atomic per CTA
#pragma unroll
    for (int o = 16; o; o >>= 1)
        val += __shfl_xor_sync(FULL, val, o);

    __shared__ float ws[8];
    if ((threadIdx.x & 31) == 0) ws[threadIdx.x >> 5] = val;
    __syncthreads();
    if (threadIdx.x == 0) {
        float t = ws[0];
#pragma unroll
        for (int k = 1; k < 8; ++k) t += ws[k];
        atomicAdd(out, t);
    }
}

extern "C" void kernel_launch(void* const* d_in, const int* in_sizes, int n_in,
                              void* d_out, int out_size)
{
    const float* logits = (const float*)d_in[0];
    const int*   target = (const int*)d_in[1];
    float*       out    = (float*)d_out;

    k_rowdist<<<(B * H) / 8, 256>>>(target, out);

    // Stage 2 with Programmatic Dependent Launch: its prelude overlaps the
    // tail of stage 1; cudaGridDependencySynchronize() guards dr2 reads.
    cudaLaunchConfig_t cfg = {};
    cfg.gridDim  = dim3(NV4 / 256);
    cfg.blockDim = dim3(256);
    cfg.dynamicSmemBytes = 0;
    cfg.stream = 0;                     // legacy default stream (captured)
    cudaLaunchAttribute attr[1];
    attr[0].id = cudaLaunchAttributeProgrammaticStreamSerialization;
    attr[0].val.programmaticStreamSerializationAllowed = 1;
    cfg.attrs = attr;
    cfg.numAttrs = 1;
    cudaLaunchKernelEx(&cfg, k_edt_loss, logits, out);
}